// round 1
// baseline (speedup 1.0000x reference)
#include <cuda_runtime.h>
#include <math.h>

// Problem constants
#define Bn   128
#define Sn   256
#define Dn   256
#define Hn   6
#define HSn  42
#define HC   252        // Hn*HSn
#define NQKV 756        // 3*HC
#define DFFn 1024
#define Mrows 32768     // Bn*Sn
#define HSP  44         // HS padded to float4 multiple

// ---------------------------------------------------------------------------
// Scratch (allocation-free: __device__ globals)
// ---------------------------------------------------------------------------
__device__ float g_qkv  [(size_t)Mrows * NQKV];   // [M, 756]  q|k|v head-concat
__device__ float g_heads[(size_t)Mrows * Dn];     // [M, 256]  head_cat padded (cols 252..255 = 0)
__device__ float g_res1 [(size_t)Mrows * Dn];     // x + attn_out (pre-LN1)
__device__ float g_ln1  [(size_t)Mrows * Dn];     // LN1 output
__device__ float g_ff1  [(size_t)Mrows * DFFn];   // relu(ln1 @ W1 + b1)
__device__ float g_res2 [(size_t)Mrows * Dn];     // ln1 + ff (pre-LN2)
__device__ float g_wqkv [Dn * NQKV];              // packed [D, 756]
__device__ float g_wproj[Dn * Dn];                // Wproj padded to [256, 256]

// ---------------------------------------------------------------------------
// Weight packing: Wq/Wk/Wv [H,D,HS] -> [D, 756]; Wproj [252,256] -> [256,256]
// ---------------------------------------------------------------------------
__global__ void pack_kernel(const float* __restrict__ Wq, const float* __restrict__ Wk,
                            const float* __restrict__ Wv, const float* __restrict__ Wproj,
                            float* __restrict__ wqkv, float* __restrict__ wproj_p) {
    int idx = blockIdx.x * 256 + threadIdx.x;
    if (idx < Dn * NQKV) {
        int d = idx / NQKV, j = idx % NQKV;
        int which = j / HC;
        int r = j - which * HC;
        int h = r / HSn, c = r - h * HSn;
        const float* W = (which == 0) ? Wq : (which == 1) ? Wk : Wv;
        wqkv[idx] = W[(h * Dn + d) * HSn + c];
    }
    if (idx < Dn * Dn) {
        int r = idx / Dn, c = idx % Dn;
        wproj_p[idx] = (r < HC) ? Wproj[r * Dn + c] : 0.0f;
    }
}

// ---------------------------------------------------------------------------
// Generic fp32 GEMM: C[M,N] = A[M,K] @ B[K,N] (+ epilogue)
// BM=128, BN=64, BK=16, 256 threads, 8x4 outputs/thread.
// Requires K % 16 == 0 and A/B rows float4-aligned (true for all call sites).
// MODE 0: raw; MODE 1: relu(acc+bias); MODE 2: acc+bias+resid (resid ld == N)
// ---------------------------------------------------------------------------
template<int MODE>
__global__ __launch_bounds__(256) void gemm_kernel(
    const float* __restrict__ A, const float* __restrict__ B, float* __restrict__ C,
    const float* __restrict__ bias, const float* __restrict__ resid,
    int M, int N, int K)
{
    __shared__ float As[16][132];   // transposed A tile, padded
    __shared__ float Bs[16][64];

    int tid = threadIdx.x;
    int tx = tid & 15;              // N direction (16 x 4 = 64)
    int ty = tid >> 4;              // M direction (16 x 8 = 128)
    int bm = blockIdx.y * 128;
    int bn = blockIdx.x * 64;

    float acc[8][4];
#pragma unroll
    for (int i = 0; i < 8; i++)
#pragma unroll
        for (int j = 0; j < 4; j++) acc[i][j] = 0.0f;

    for (int k0 = 0; k0 < K; k0 += 16) {
        // Load A tile (128x16) transposed into smem: 512 float4, 2 per thread
#pragma unroll
        for (int i = 0; i < 2; i++) {
            int idx = tid + i * 256;
            int r = idx >> 2;              // 0..127 (tile row)
            int c4 = (idx & 3) << 2;       // 0,4,8,12
            float4 v = *(const float4*)(A + (size_t)(bm + r) * K + k0 + c4);
            As[c4 + 0][r] = v.x;
            As[c4 + 1][r] = v.y;
            As[c4 + 2][r] = v.z;
            As[c4 + 3][r] = v.w;
        }
        // Load B tile (16x64): 256 float4, 1 per thread
        {
            int r = tid >> 4;              // 0..15 (k)
            int c4 = (tid & 15) << 2;      // 0..60
            int gn = bn + c4;
            float4 v = make_float4(0.f, 0.f, 0.f, 0.f);
            if (gn < N)                    // N % 4 == 0 -> whole float4 in range
                v = *(const float4*)(B + (size_t)(k0 + r) * N + gn);
            *(float4*)&Bs[r][c4] = v;
        }
        __syncthreads();

#pragma unroll
        for (int kk = 0; kk < 16; kk++) {
            float4 a0 = *(const float4*)&As[kk][ty * 8];
            float4 a1 = *(const float4*)&As[kk][ty * 8 + 4];
            float4 bv = *(const float4*)&Bs[kk][tx * 4];
            float a[8] = {a0.x, a0.y, a0.z, a0.w, a1.x, a1.y, a1.z, a1.w};
            float bb[4] = {bv.x, bv.y, bv.z, bv.w};
#pragma unroll
            for (int i = 0; i < 8; i++)
#pragma unroll
                for (int j = 0; j < 4; j++)
                    acc[i][j] = fmaf(a[i], bb[j], acc[i][j]);
        }
        __syncthreads();
    }

#pragma unroll
    for (int i = 0; i < 8; i++) {
        int gm = bm + ty * 8 + i;
        size_t rowoff = (size_t)gm * N;
#pragma unroll
        for (int j = 0; j < 4; j++) {
            int gn = bn + tx * 4 + j;
            if (gn < N) {
                float v = acc[i][j];
                if (MODE == 1) v = fmaxf(v + bias[gn], 0.0f);
                if (MODE == 2) v = v + bias[gn] + resid[rowoff + gn];
                C[rowoff + gn] = v;
            }
        }
    }
}

// ---------------------------------------------------------------------------
// Causal attention: one block per (b,h); thread t = query row t.
// K,V tiles in smem (padded to 44 floats/row); online softmax in registers.
// ---------------------------------------------------------------------------
__global__ __launch_bounds__(256) void attn_kernel(const float* __restrict__ qkv,
                                                   float* __restrict__ heads) {
    extern __shared__ float sm[];
    float* Ks = sm;                 // 256 * 44
    float* Vs = sm + Sn * HSP;      // 256 * 44

    int b = blockIdx.x, h = blockIdx.y;
    int tid = threadIdx.x;
    const float* base = qkv + (size_t)b * Sn * NQKV;

    // Cooperative K/V load (coalesced-ish over columns)
    for (int idx = tid; idx < Sn * HSn; idx += 256) {
        int r = idx / HSn, c = idx - r * HSn;
        Ks[r * HSP + c] = base[(size_t)r * NQKV + HC + h * HSn + c];
        Vs[r * HSP + c] = base[(size_t)r * NQKV + 2 * HC + h * HSn + c];
    }
    Ks[tid * HSP + 42] = 0.f; Ks[tid * HSP + 43] = 0.f;
    Vs[tid * HSP + 42] = 0.f; Vs[tid * HSP + 43] = 0.f;

    const float scale = rsqrtf((float)HSn);   // 1/sqrt(42)
    float q[HSP];
    {
        const float* qp = base + (size_t)tid * NQKV + h * HSn;
#pragma unroll
        for (int c = 0; c < HSn; c++) q[c] = qp[c] * scale;
        q[42] = 0.f; q[43] = 0.f;
    }
    __syncthreads();

    float m = -INFINITY, l = 0.0f;
    float o[HSP];
#pragma unroll
    for (int c = 0; c < HSP; c++) o[c] = 0.0f;

    for (int j = 0; j <= tid; j++) {           // causal: keys 0..t
        const float4* kr = (const float4*)(Ks + j * HSP);
        float s = 0.0f;
#pragma unroll
        for (int u = 0; u < 11; u++) {
            float4 kv = kr[u];
            s += q[4*u] * kv.x + q[4*u+1] * kv.y + q[4*u+2] * kv.z + q[4*u+3] * kv.w;
        }
        if (s > m) {                            // rescale only when max moves
            float corr = __expf(m - s);         // exp(-inf)=0 handles first iter
            l *= corr;
#pragma unroll
            for (int c = 0; c < HSP; c++) o[c] *= corr;
            m = s;
        }
        float p = __expf(s - m);
        l += p;
        const float4* vr = (const float4*)(Vs + j * HSP);
#pragma unroll
        for (int u = 0; u < 11; u++) {
            float4 vv = vr[u];
            o[4*u]   = fmaf(p, vv.x, o[4*u]);
            o[4*u+1] = fmaf(p, vv.y, o[4*u+1]);
            o[4*u+2] = fmaf(p, vv.z, o[4*u+2]);
            o[4*u+3] = fmaf(p, vv.w, o[4*u+3]);
        }
    }

    float inv = 1.0f / l;
    float* op = heads + ((size_t)(b * Sn + tid)) * Dn + h * HSn;
#pragma unroll
    for (int c = 0; c < HSn; c++) op[c] = o[c] * inv;
    if (h == 0) {                               // zero the padded cols 252..255
        float* zp = heads + ((size_t)(b * Sn + tid)) * Dn;
        zp[252] = 0.f; zp[253] = 0.f; zp[254] = 0.f; zp[255] = 0.f;
    }
}

// ---------------------------------------------------------------------------
// LayerNorm over last dim (256): one warp per row.
// ---------------------------------------------------------------------------
__global__ void ln_kernel(const float* __restrict__ in, const float* __restrict__ g,
                          const float* __restrict__ bb, float* __restrict__ out) {
    int row = blockIdx.x * blockDim.y + threadIdx.y;
    int lane = threadIdx.x;
    const float4* x = (const float4*)(in + (size_t)row * Dn);
    float4 a = x[lane];
    float4 c = x[lane + 32];
    float s  = a.x + a.y + a.z + a.w + c.x + c.y + c.z + c.w;
    float ss = a.x*a.x + a.y*a.y + a.z*a.z + a.w*a.w
             + c.x*c.x + c.y*c.y + c.z*c.z + c.w*c.w;
#pragma unroll
    for (int off = 16; off > 0; off >>= 1) {
        s  += __shfl_xor_sync(0xffffffffu, s,  off);
        ss += __shfl_xor_sync(0xffffffffu, ss, off);
    }
    float mean = s * (1.0f / 256.0f);
    float var  = ss * (1.0f / 256.0f) - mean * mean;
    float rstd = rsqrtf(var + 1e-5f);
    float4 g1 = ((const float4*)g)[lane],  g2 = ((const float4*)g)[lane + 32];
    float4 b1 = ((const float4*)bb)[lane], b2 = ((const float4*)bb)[lane + 32];
    float4 r1, r2;
    r1.x = (a.x - mean) * rstd * g1.x + b1.x;
    r1.y = (a.y - mean) * rstd * g1.y + b1.y;
    r1.z = (a.z - mean) * rstd * g1.z + b1.z;
    r1.w = (a.w - mean) * rstd * g1.w + b1.w;
    r2.x = (c.x - mean) * rstd * g2.x + b2.x;
    r2.y = (c.y - mean) * rstd * g2.y + b2.y;
    r2.z = (c.z - mean) * rstd * g2.z + b2.z;
    r2.w = (c.w - mean) * rstd * g2.w + b2.w;
    float4* o4 = (float4*)(out + (size_t)row * Dn);
    o4[lane] = r1;
    o4[lane + 32] = r2;
}

// ---------------------------------------------------------------------------
// Launch
// ---------------------------------------------------------------------------
extern "C" void kernel_launch(void* const* d_in, const int* in_sizes, int n_in,
                              void* d_out, int out_size) {
    const float* x     = (const float*)d_in[0];
    const float* Wq    = (const float*)d_in[1];
    const float* Wk    = (const float*)d_in[2];
    const float* Wv    = (const float*)d_in[3];
    const float* Wproj = (const float*)d_in[4];
    const float* bproj = (const float*)d_in[5];
    const float* ln1_g = (const float*)d_in[6];
    const float* ln1_b = (const float*)d_in[7];
    const float* W1    = (const float*)d_in[8];
    const float* b1    = (const float*)d_in[9];
    const float* W2    = (const float*)d_in[10];
    const float* b2    = (const float*)d_in[11];
    const float* ln2_g = (const float*)d_in[12];
    const float* ln2_b = (const float*)d_in[13];
    float* out = (float*)d_out;

    float *qkv, *heads, *res1, *ln1, *ff1, *res2, *wqkv, *wproj;
    cudaGetSymbolAddress((void**)&qkv,   g_qkv);
    cudaGetSymbolAddress((void**)&heads, g_heads);
    cudaGetSymbolAddress((void**)&res1,  g_res1);
    cudaGetSymbolAddress((void**)&ln1,   g_ln1);
    cudaGetSymbolAddress((void**)&ff1,   g_ff1);
    cudaGetSymbolAddress((void**)&res2,  g_res2);
    cudaGetSymbolAddress((void**)&wqkv,  g_wqkv);
    cudaGetSymbolAddress((void**)&wproj, g_wproj);

    int smem_attn = 2 * Sn * HSP * (int)sizeof(float);   // 90112 B
    cudaFuncSetAttribute(attn_kernel, cudaFuncAttributeMaxDynamicSharedMemorySize, smem_attn);

    // 1. pack weights
    pack_kernel<<<756, 256>>>(Wq, Wk, Wv, Wproj, wqkv, wproj);
    // 2. QKV:   [32768,256] @ [256,756]
    gemm_kernel<0><<<dim3(12, 256), 256>>>(x, wqkv, qkv, nullptr, nullptr, Mrows, NQKV, Dn);
    // 3. attention -> head_cat (padded to 256 cols)
    attn_kernel<<<dim3(Bn, Hn), 256, smem_attn>>>(qkv, heads);
    // 4. proj + residual(x):  [32768,256] @ [256,256]
    gemm_kernel<2><<<dim3(4, 256), 256>>>(heads, wproj, res1, bproj, x, Mrows, Dn, Dn);
    // 5. LN1
    ln_kernel<<<Mrows / 8, dim3(32, 8)>>>(res1, ln1_g, ln1_b, ln1);
    // 6. FFN1 + ReLU:  [32768,256] @ [256,1024]
    gemm_kernel<1><<<dim3(16, 256), 256>>>(ln1, W1, ff1, b1, nullptr, Mrows, DFFn, Dn);
    // 7. FFN2 + residual(ln1): [32768,1024] @ [1024,256]
    gemm_kernel<2><<<dim3(4, 256), 256>>>(ff1, W2, res2, b2, ln1, Mrows, Dn, DFFn);
    // 8. LN2 -> output
    ln_kernel<<<Mrows / 8, dim3(32, 8)>>>(res2, ln2_g, ln2_b, out);
}

// round 2
// speedup vs baseline: 1.0161x; 1.0161x over previous
#include <cuda_runtime.h>
#include <math.h>

// Problem constants
#define Bn   128
#define Sn   256
#define Dn   256
#define Hn   6
#define HSn  42
#define HC   252        // Hn*HSn
#define NQKV 756        // 3*HC
#define DFFn 1024
#define Mrows 32768     // Bn*Sn
#define HSP  44         // HS padded to float4 multiple

// ---------------------------------------------------------------------------
// Scratch (allocation-free: __device__ globals)
// ---------------------------------------------------------------------------
__device__ float g_qkv  [(size_t)Mrows * NQKV];   // [M, 756]  q|k|v head-concat
__device__ float g_heads[(size_t)Mrows * Dn];     // [M, 256]  head_cat padded (cols 252..255 = 0)
__device__ float g_res1 [(size_t)Mrows * Dn];     // x + attn_out (pre-LN1)
__device__ float g_ln1  [(size_t)Mrows * Dn];     // LN1 output
__device__ float g_ff1  [(size_t)Mrows * DFFn];   // relu(ln1 @ W1 + b1)
__device__ float g_res2 [(size_t)Mrows * Dn];     // ln1 + ff (pre-LN2)
__device__ float g_wqkv [Dn * NQKV];              // packed [D, 756]
__device__ float g_wproj[Dn * Dn];                // Wproj padded to [256, 256]

// ---------------------------------------------------------------------------
// Weight packing: Wq/Wk/Wv [H,D,HS] -> [D, 756]; Wproj [252,256] -> [256,256]
// ---------------------------------------------------------------------------
__global__ void pack_kernel(const float* __restrict__ Wq, const float* __restrict__ Wk,
                            const float* __restrict__ Wv, const float* __restrict__ Wproj,
                            float* __restrict__ wqkv, float* __restrict__ wproj_p) {
    int idx = blockIdx.x * 256 + threadIdx.x;
    if (idx < Dn * NQKV) {
        int d = idx / NQKV, j = idx % NQKV;
        int which = j / HC;
        int r = j - which * HC;
        int h = r / HSn, c = r - h * HSn;
        const float* W = (which == 0) ? Wq : (which == 1) ? Wk : Wv;
        wqkv[idx] = W[(h * Dn + d) * HSn + c];
    }
    if (idx < Dn * Dn) {
        int r = idx / Dn, c = idx % Dn;
        wproj_p[idx] = (r < HC) ? Wproj[r * Dn + c] : 0.0f;
    }
}

// ---------------------------------------------------------------------------
// Generic fp32 GEMM: C[M,N] = A[M,K] @ B[K,N] (+ epilogue)
// BM=128, BN=64, BK=16, 256 threads, 8x4 outputs/thread.
// MODE 0: raw; MODE 1: relu(acc+bias); MODE 2: acc+bias+resid (resid ld == N)
// ---------------------------------------------------------------------------
template<int MODE>
__global__ __launch_bounds__(256) void gemm_kernel(
    const float* __restrict__ A, const float* __restrict__ B, float* __restrict__ C,
    const float* __restrict__ bias, const float* __restrict__ resid,
    int M, int N, int K)
{
    __shared__ float As[16][132];   // transposed A tile, padded
    __shared__ float Bs[16][64];

    int tid = threadIdx.x;
    int tx = tid & 15;              // N direction (16 x 4 = 64)
    int ty = tid >> 4;              // M direction (16 x 8 = 128)
    int bm = blockIdx.y * 128;
    int bn = blockIdx.x * 64;

    float acc[8][4];
#pragma unroll
    for (int i = 0; i < 8; i++)
#pragma unroll
        for (int j = 0; j < 4; j++) acc[i][j] = 0.0f;

    for (int k0 = 0; k0 < K; k0 += 16) {
#pragma unroll
        for (int i = 0; i < 2; i++) {
            int idx = tid + i * 256;
            int r = idx >> 2;              // 0..127 (tile row)
            int c4 = (idx & 3) << 2;       // 0,4,8,12
            float4 v = *(const float4*)(A + (size_t)(bm + r) * K + k0 + c4);
            As[c4 + 0][r] = v.x;
            As[c4 + 1][r] = v.y;
            As[c4 + 2][r] = v.z;
            As[c4 + 3][r] = v.w;
        }
        {
            int r = tid >> 4;              // 0..15 (k)
            int c4 = (tid & 15) << 2;      // 0..60
            int gn = bn + c4;
            float4 v = make_float4(0.f, 0.f, 0.f, 0.f);
            if (gn < N)
                v = *(const float4*)(B + (size_t)(k0 + r) * N + gn);
            *(float4*)&Bs[r][c4] = v;
        }
        __syncthreads();

#pragma unroll
        for (int kk = 0; kk < 16; kk++) {
            float4 a0 = *(const float4*)&As[kk][ty * 8];
            float4 a1 = *(const float4*)&As[kk][ty * 8 + 4];
            float4 bv = *(const float4*)&Bs[kk][tx * 4];
            float a[8] = {a0.x, a0.y, a0.z, a0.w, a1.x, a1.y, a1.z, a1.w};
            float bb[4] = {bv.x, bv.y, bv.z, bv.w};
#pragma unroll
            for (int i = 0; i < 8; i++)
#pragma unroll
                for (int j = 0; j < 4; j++)
                    acc[i][j] = fmaf(a[i], bb[j], acc[i][j]);
        }
        __syncthreads();
    }

#pragma unroll
    for (int i = 0; i < 8; i++) {
        int gm = bm + ty * 8 + i;
        size_t rowoff = (size_t)gm * N;
#pragma unroll
        for (int j = 0; j < 4; j++) {
            int gn = bn + tx * 4 + j;
            if (gn < N) {
                float v = acc[i][j];
                if (MODE == 1) v = fmaxf(v + bias[gn], 0.0f);
                if (MODE == 2) v = v + bias[gn] + resid[rowoff + gn];
                C[rowoff + gn] = v;
            }
        }
    }
}

// ---------------------------------------------------------------------------
// Causal attention v2: one block per (b,h); thread t = query row t.
// Softmax stabilized with a Cauchy-Schwarz upper bound m0 = |q||k|_max
// computed once per block -> NO online max, NO rescale, NO branch in the
// inner loop. 4-way split score accumulator breaks the dependency chain.
// __launch_bounds__(256,2) caps regs at 128 -> 2 blocks/SM (16 warps).
// ---------------------------------------------------------------------------
__global__ __launch_bounds__(256, 2) void attn_kernel(const float* __restrict__ qkv,
                                                      float* __restrict__ heads) {
    extern __shared__ float sm[];
    float* Ks = sm;                 // 256 * 44
    float* Vs = sm + Sn * HSP;      // 256 * 44
    __shared__ float red[8];

    int b = blockIdx.x, h = blockIdx.y;
    int tid = threadIdx.x;
    const float* base = qkv + (size_t)b * Sn * NQKV;

    // Cooperative K/V load
    for (int idx = tid; idx < Sn * HSn; idx += 256) {
        int r = idx / HSn, c = idx - r * HSn;
        Ks[r * HSP + c] = base[(size_t)r * NQKV + HC + h * HSn + c];
        Vs[r * HSP + c] = base[(size_t)r * NQKV + 2 * HC + h * HSn + c];
    }
    Ks[tid * HSP + 42] = 0.f; Ks[tid * HSP + 43] = 0.f;
    Vs[tid * HSP + 42] = 0.f; Vs[tid * HSP + 43] = 0.f;

    const float scale = rsqrtf(42.0f);
    float q[HSP];
    {
        const float* qp = base + (size_t)tid * NQKV + h * HSn;
#pragma unroll
        for (int c = 0; c < HSn; c++) q[c] = qp[c] * scale;
        q[42] = 0.f; q[43] = 0.f;
    }
    __syncthreads();

    // Block max of |k_row|^2 (thread tid owns row tid)
    float kn = 0.f;
    {
        const float4* kr0 = (const float4*)(Ks + tid * HSP);
#pragma unroll
        for (int u = 0; u < 11; u++) {
            float4 kv = kr0[u];
            kn += kv.x * kv.x + kv.y * kv.y + kv.z * kv.z + kv.w * kv.w;
        }
    }
#pragma unroll
    for (int off = 16; off > 0; off >>= 1)
        kn = fmaxf(kn, __shfl_xor_sync(0xffffffffu, kn, off));
    if ((tid & 31) == 0) red[tid >> 5] = kn;
    __syncthreads();
    float kmax2 = fmaxf(fmaxf(fmaxf(red[0], red[1]), fmaxf(red[2], red[3])),
                        fmaxf(fmaxf(red[4], red[5]), fmaxf(red[6], red[7])));

    float qn2 = 0.f;
#pragma unroll
    for (int c = 0; c < HSn; c++) qn2 = fmaf(q[c], q[c], qn2);
    // m0 >= every score s = q_scaled . k  (Cauchy-Schwarz)
    float m0 = sqrtf(qn2 * kmax2);

    float l = 0.0f;
    float o[HSP];
#pragma unroll
    for (int c = 0; c < HSP; c++) o[c] = 0.0f;

    for (int j = 0; j <= tid; j++) {           // causal: keys 0..t
        const float4* kr = (const float4*)(Ks + j * HSP);
        float s0 = 0.f, s1 = 0.f, s2 = 0.f, s3 = 0.f;
#pragma unroll
        for (int u = 0; u < 11; u++) {
            float4 kv = kr[u];
            s0 = fmaf(q[4*u],   kv.x, s0);
            s1 = fmaf(q[4*u+1], kv.y, s1);
            s2 = fmaf(q[4*u+2], kv.z, s2);
            s3 = fmaf(q[4*u+3], kv.w, s3);
        }
        float s = (s0 + s1) + (s2 + s3);
        float p = __expf(fmaxf(s - m0, -80.0f));   // s <= m0 always; clamp = NaN insurance
        l += p;
        const float4* vr = (const float4*)(Vs + j * HSP);
#pragma unroll
        for (int u = 0; u < 11; u++) {
            float4 vv = vr[u];
            o[4*u]   = fmaf(p, vv.x, o[4*u]);
            o[4*u+1] = fmaf(p, vv.y, o[4*u+1]);
            o[4*u+2] = fmaf(p, vv.z, o[4*u+2]);
            o[4*u+3] = fmaf(p, vv.w, o[4*u+3]);
        }
    }

    float inv = 1.0f / l;
    float* op = heads + ((size_t)(b * Sn + tid)) * Dn + h * HSn;
#pragma unroll
    for (int c = 0; c < HSn; c++) op[c] = o[c] * inv;
    if (h == 0) {                               // zero the padded cols 252..255
        float* zp = heads + ((size_t)(b * Sn + tid)) * Dn;
        zp[252] = 0.f; zp[253] = 0.f; zp[254] = 0.f; zp[255] = 0.f;
    }
}

// ---------------------------------------------------------------------------
// LayerNorm over last dim (256): one warp per row.
// ---------------------------------------------------------------------------
__global__ void ln_kernel(const float* __restrict__ in, const float* __restrict__ g,
                          const float* __restrict__ bb, float* __restrict__ out) {
    int row = blockIdx.x * blockDim.y + threadIdx.y;
    int lane = threadIdx.x;
    const float4* x = (const float4*)(in + (size_t)row * Dn);
    float4 a = x[lane];
    float4 c = x[lane + 32];
    float s  = a.x + a.y + a.z + a.w + c.x + c.y + c.z + c.w;
    float ss = a.x*a.x + a.y*a.y + a.z*a.z + a.w*a.w
             + c.x*c.x + c.y*c.y + c.z*c.z + c.w*c.w;
#pragma unroll
    for (int off = 16; off > 0; off >>= 1) {
        s  += __shfl_xor_sync(0xffffffffu, s,  off);
        ss += __shfl_xor_sync(0xffffffffu, ss, off);
    }
    float mean = s * (1.0f / 256.0f);
    float var  = ss * (1.0f / 256.0f) - mean * mean;
    float rstd = rsqrtf(var + 1e-5f);
    float4 g1 = ((const float4*)g)[lane],  g2 = ((const float4*)g)[lane + 32];
    float4 b1 = ((const float4*)bb)[lane], b2 = ((const float4*)bb)[lane + 32];
    float4 r1, r2;
    r1.x = (a.x - mean) * rstd * g1.x + b1.x;
    r1.y = (a.y - mean) * rstd * g1.y + b1.y;
    r1.z = (a.z - mean) * rstd * g1.z + b1.z;
    r1.w = (a.w - mean) * rstd * g1.w + b1.w;
    r2.x = (c.x - mean) * rstd * g2.x + b2.x;
    r2.y = (c.y - mean) * rstd * g2.y + b2.y;
    r2.z = (c.z - mean) * rstd * g2.z + b2.z;
    r2.w = (c.w - mean) * rstd * g2.w + b2.w;
    float4* o4 = (float4*)(out + (size_t)row * Dn);
    o4[lane] = r1;
    o4[lane + 32] = r2;
}

// ---------------------------------------------------------------------------
// Launch
// ---------------------------------------------------------------------------
extern "C" void kernel_launch(void* const* d_in, const int* in_sizes, int n_in,
                              void* d_out, int out_size) {
    const float* x     = (const float*)d_in[0];
    const float* Wq    = (const float*)d_in[1];
    const float* Wk    = (const float*)d_in[2];
    const float* Wv    = (const float*)d_in[3];
    const float* Wproj = (const float*)d_in[4];
    const float* bproj = (const float*)d_in[5];
    const float* ln1_g = (const float*)d_in[6];
    const float* ln1_b = (const float*)d_in[7];
    const float* W1    = (const float*)d_in[8];
    const float* b1    = (const float*)d_in[9];
    const float* W2    = (const float*)d_in[10];
    const float* b2    = (const float*)d_in[11];
    const float* ln2_g = (const float*)d_in[12];
    const float* ln2_b = (const float*)d_in[13];
    float* out = (float*)d_out;

    float *qkv, *heads, *res1, *ln1, *ff1, *res2, *wqkv, *wproj;
    cudaGetSymbolAddress((void**)&qkv,   g_qkv);
    cudaGetSymbolAddress((void**)&heads, g_heads);
    cudaGetSymbolAddress((void**)&res1,  g_res1);
    cudaGetSymbolAddress((void**)&ln1,   g_ln1);
    cudaGetSymbolAddress((void**)&ff1,   g_ff1);
    cudaGetSymbolAddress((void**)&res2,  g_res2);
    cudaGetSymbolAddress((void**)&wqkv,  g_wqkv);
    cudaGetSymbolAddress((void**)&wproj, g_wproj);

    int smem_attn = 2 * Sn * HSP * (int)sizeof(float);   // 90112 B
    cudaFuncSetAttribute(attn_kernel, cudaFuncAttributeMaxDynamicSharedMemorySize, smem_attn);

    // 1. pack weights
    pack_kernel<<<756, 256>>>(Wq, Wk, Wv, Wproj, wqkv, wproj);
    // 2. QKV:   [32768,256] @ [256,756]
    gemm_kernel<0><<<dim3(12, 256), 256>>>(x, wqkv, qkv, nullptr, nullptr, Mrows, NQKV, Dn);
    // 3. attention -> head_cat (padded to 256 cols)
    attn_kernel<<<dim3(Bn, Hn), 256, smem_attn>>>(qkv, heads);
    // 4. proj + residual(x):  [32768,256] @ [256,256]
    gemm_kernel<2><<<dim3(4, 256), 256>>>(heads, wproj, res1, bproj, x, Mrows, Dn, Dn);
    // 5. LN1
    ln_kernel<<<Mrows / 8, dim3(32, 8)>>>(res1, ln1_g, ln1_b, ln1);
    // 6. FFN1 + ReLU:  [32768,256] @ [256,1024]
    gemm_kernel<1><<<dim3(16, 256), 256>>>(ln1, W1, ff1, b1, nullptr, Mrows, DFFn, Dn);
    // 7. FFN2 + residual(ln1): [32768,1024] @ [1024,256]
    gemm_kernel<2><<<dim3(4, 256), 256>>>(ff1, W2, res2, b2, ln1, Mrows, Dn, DFFn);
    // 8. LN2 -> output
    ln_kernel<<<Mrows / 8, dim3(32, 8)>>>(res2, ln2_g, ln2_b, out);
}

// round 3
// speedup vs baseline: 1.8021x; 1.7736x over previous
#include <cuda_runtime.h>
#include <math.h>
#include <stdint.h>

// Problem constants
#define Bn    128
#define Sn    256
#define Dn    256
#define Hn    6
#define HSn   42
#define HC    252        // Hn*HSn
#define NQKVP 768        // 3*HC = 756, padded to 768 for tile-exact GEMM
#define DFFn  1024
#define Mrows 32768      // Bn*Sn
#define HSP   44         // HS padded to float4 multiple

// ---------------------------------------------------------------------------
// Scratch (allocation-free: __device__ globals)
// ---------------------------------------------------------------------------
__device__ float g_qkv  [(size_t)Mrows * NQKVP];  // [M, 768]  q|k|v head-concat (+pad)
__device__ float g_heads[(size_t)Mrows * Dn];     // [M, 256]  head_cat padded
__device__ float g_res1 [(size_t)Mrows * Dn];
__device__ float g_ln1  [(size_t)Mrows * Dn];
__device__ float g_ff1  [(size_t)Mrows * DFFn];
__device__ float g_res2 [(size_t)Mrows * Dn];
__device__ float g_wqkv [Dn * NQKVP];             // packed [D, 768] (cols 756..767 zero)
__device__ float g_wproj[Dn * Dn];                // Wproj padded to [256, 256]

// ---------------------------------------------------------------------------
// Weight packing
// ---------------------------------------------------------------------------
__global__ void pack_kernel(const float* __restrict__ Wq, const float* __restrict__ Wk,
                            const float* __restrict__ Wv, const float* __restrict__ Wproj,
                            float* __restrict__ wqkv, float* __restrict__ wproj_p) {
    int idx = blockIdx.x * 256 + threadIdx.x;
    if (idx < Dn * NQKVP) {
        int d = idx / NQKVP, j = idx % NQKVP;
        float val = 0.0f;
        if (j < 756) {
            int which = j / HC;
            int rr = j - which * HC;
            int h = rr / HSn, c = rr - h * HSn;
            const float* W = (which == 0) ? Wq : (which == 1) ? Wk : Wv;
            val = W[(h * Dn + d) * HSn + c];
        }
        wqkv[idx] = val;
    }
    if (idx < Dn * Dn) {
        int rr = idx / Dn, c = idx % Dn;
        wproj_p[idx] = (rr < HC) ? Wproj[rr * Dn + c] : 0.0f;
    }
}

// ---------------------------------------------------------------------------
// tf32 tensor-core GEMM: C[M,N] = A[M,K] @ B[K,N] (+ epilogue)
// BM=128, BN=64, BK=16; 256 threads = 8 warps (4 m x 2 n), warp tile 32x32.
// mma.sync.aligned.m16n8k8 tf32, fp32 accumulate. Requires M%128==0, N%64==0,
// K%16==0 (true at all call sites). Double-buffered smem.
// MODE 0: raw; MODE 1: relu(acc+bias); MODE 2: acc+bias+resid
// ---------------------------------------------------------------------------
__device__ __forceinline__ uint32_t f2tf(float f) {
    uint32_t u;
    asm("cvt.rna.tf32.f32 %0, %1;" : "=r"(u) : "f"(f));
    return u;
}

__device__ __forceinline__ void mma_tf32(float c[4], const uint32_t a[4], const uint32_t b[2]) {
    asm volatile(
        "mma.sync.aligned.m16n8k8.row.col.f32.tf32.tf32.f32 "
        "{%0,%1,%2,%3}, {%4,%5,%6,%7}, {%8,%9}, {%0,%1,%2,%3};"
        : "+f"(c[0]), "+f"(c[1]), "+f"(c[2]), "+f"(c[3])
        : "r"(a[0]), "r"(a[1]), "r"(a[2]), "r"(a[3]), "r"(b[0]), "r"(b[1]));
}

#define LDA 20   // A smem row pitch (16 + 4 pad): conflict-free frag loads
#define LDB 72   // B smem row pitch (64 + 8 pad)

template<int MODE>
__global__ __launch_bounds__(256) void gemm_tc(
    const float* __restrict__ A, const float* __restrict__ B, float* __restrict__ C,
    const float* __restrict__ bias, const float* __restrict__ resid,
    int M, int N, int K)
{
    __shared__ uint32_t As[2][128 * LDA];
    __shared__ uint32_t Bs[2][16 * LDB];

    int tid  = threadIdx.x;
    int lane = tid & 31, wid = tid >> 5;
    int wm = wid & 3, wn = wid >> 2;          // 4 x 2 warp grid
    int bm = blockIdx.y * 128, bn = blockIdx.x * 64;
    int r  = lane >> 2, cq = lane & 3;        // frag lane coords

    float acc[2][4][4];
#pragma unroll
    for (int mf = 0; mf < 2; mf++)
#pragma unroll
        for (int nf = 0; nf < 4; nf++)
#pragma unroll
            for (int i = 0; i < 4; i++) acc[mf][nf][i] = 0.0f;

    // global-load / smem-store coordinates
    int a_r = tid >> 2;                  // 0..63 (+64 for second half)
    int a_c = (tid & 3) << 2;            // 0,4,8,12
    int b_r = tid >> 4;                  // 0..15
    int b_c = (tid & 15) << 2;           // 0..60

    const float* Ag0 = A + (size_t)(bm + a_r) * K + a_c;
    const float* Ag1 = A + (size_t)(bm + a_r + 64) * K + a_c;
    const float* Bg  = B + (size_t)b_r * N + bn + b_c;

    float4 ra0, ra1, rb;

    // prologue: tile 0
    ra0 = *(const float4*)(Ag0);
    ra1 = *(const float4*)(Ag1);
    rb  = *(const float4*)(Bg);
    {
        uint4 u0 = make_uint4(f2tf(ra0.x), f2tf(ra0.y), f2tf(ra0.z), f2tf(ra0.w));
        uint4 u1 = make_uint4(f2tf(ra1.x), f2tf(ra1.y), f2tf(ra1.z), f2tf(ra1.w));
        uint4 ub = make_uint4(f2tf(rb.x),  f2tf(rb.y),  f2tf(rb.z),  f2tf(rb.w));
        *(uint4*)&As[0][a_r * LDA + a_c]        = u0;
        *(uint4*)&As[0][(a_r + 64) * LDA + a_c] = u1;
        *(uint4*)&Bs[0][b_r * LDB + b_c]        = ub;
    }
    __syncthreads();

    int nk = K >> 4;
    for (int it = 0; it < nk; it++) {
        int cur = it & 1, nxt = cur ^ 1;
        bool more = (it + 1 < nk);
        if (more) {
            int k0 = (it + 1) << 4;
            ra0 = *(const float4*)(Ag0 + k0);
            ra1 = *(const float4*)(Ag1 + k0);
            rb  = *(const float4*)(Bg + (size_t)k0 * N);
        }

        // compute current tile: 2 k-frags of 8
#pragma unroll
        for (int kk = 0; kk < 16; kk += 8) {
            uint32_t a[2][4], b[4][2];
#pragma unroll
            for (int mf = 0; mf < 2; mf++) {
                int ar = (wm * 32 + mf * 16 + r) * LDA + kk + cq;
                a[mf][0] = As[cur][ar];
                a[mf][1] = As[cur][ar + 8 * LDA];
                a[mf][2] = As[cur][ar + 4];
                a[mf][3] = As[cur][ar + 8 * LDA + 4];
            }
#pragma unroll
            for (int nf = 0; nf < 4; nf++) {
                int bc = (kk + cq) * LDB + wn * 32 + nf * 8 + r;
                b[nf][0] = Bs[cur][bc];
                b[nf][1] = Bs[cur][bc + 4 * LDB];
            }
#pragma unroll
            for (int mf = 0; mf < 2; mf++)
#pragma unroll
                for (int nf = 0; nf < 4; nf++)
                    mma_tf32(acc[mf][nf], a[mf], b[nf]);
        }

        if (more) {
            uint4 u0 = make_uint4(f2tf(ra0.x), f2tf(ra0.y), f2tf(ra0.z), f2tf(ra0.w));
            uint4 u1 = make_uint4(f2tf(ra1.x), f2tf(ra1.y), f2tf(ra1.z), f2tf(ra1.w));
            uint4 ub = make_uint4(f2tf(rb.x),  f2tf(rb.y),  f2tf(rb.z),  f2tf(rb.w));
            *(uint4*)&As[nxt][a_r * LDA + a_c]        = u0;
            *(uint4*)&As[nxt][(a_r + 64) * LDA + a_c] = u1;
            *(uint4*)&Bs[nxt][b_r * LDB + b_c]        = ub;
        }
        __syncthreads();
    }

    // epilogue
#pragma unroll
    for (int mf = 0; mf < 2; mf++) {
#pragma unroll
        for (int nf = 0; nf < 4; nf++) {
            int row = bm + wm * 32 + mf * 16 + r;
            int col = bn + wn * 32 + nf * 8 + cq * 2;
            float v0 = acc[mf][nf][0], v1 = acc[mf][nf][1];
            float v2 = acc[mf][nf][2], v3 = acc[mf][nf][3];
            size_t o0 = (size_t)row * N + col;
            size_t o1 = (size_t)(row + 8) * N + col;
            if (MODE == 1) {
                float b0 = bias[col], b1 = bias[col + 1];
                v0 = fmaxf(v0 + b0, 0.f); v1 = fmaxf(v1 + b1, 0.f);
                v2 = fmaxf(v2 + b0, 0.f); v3 = fmaxf(v3 + b1, 0.f);
            }
            if (MODE == 2) {
                float b0 = bias[col], b1 = bias[col + 1];
                float2 r0 = *(const float2*)(resid + o0);
                float2 r1 = *(const float2*)(resid + o1);
                v0 += b0 + r0.x; v1 += b1 + r0.y;
                v2 += b0 + r1.x; v3 += b1 + r1.y;
            }
            *(float2*)(C + o0) = make_float2(v0, v1);
            *(float2*)(C + o1) = make_float2(v2, v3);
        }
    }
}

// ---------------------------------------------------------------------------
// Causal attention (unchanged from round 2, stride updated to 768)
// ---------------------------------------------------------------------------
__global__ __launch_bounds__(256, 2) void attn_kernel(const float* __restrict__ qkv,
                                                      float* __restrict__ heads) {
    extern __shared__ float sm[];
    float* Ks = sm;                 // 256 * 44
    float* Vs = sm + Sn * HSP;      // 256 * 44
    __shared__ float red[8];

    int b = blockIdx.x, h = blockIdx.y;
    int tid = threadIdx.x;
    const float* base = qkv + (size_t)b * Sn * NQKVP;

    for (int idx = tid; idx < Sn * HSn; idx += 256) {
        int rr = idx / HSn, c = idx - rr * HSn;
        Ks[rr * HSP + c] = base[(size_t)rr * NQKVP + HC + h * HSn + c];
        Vs[rr * HSP + c] = base[(size_t)rr * NQKVP + 2 * HC + h * HSn + c];
    }
    Ks[tid * HSP + 42] = 0.f; Ks[tid * HSP + 43] = 0.f;
    Vs[tid * HSP + 42] = 0.f; Vs[tid * HSP + 43] = 0.f;

    const float scale = rsqrtf(42.0f);
    float q[HSP];
    {
        const float* qp = base + (size_t)tid * NQKVP + h * HSn;
#pragma unroll
        for (int c = 0; c < HSn; c++) q[c] = qp[c] * scale;
        q[42] = 0.f; q[43] = 0.f;
    }
    __syncthreads();

    float kn = 0.f;
    {
        const float4* kr0 = (const float4*)(Ks + tid * HSP);
#pragma unroll
        for (int u = 0; u < 11; u++) {
            float4 kv = kr0[u];
            kn += kv.x * kv.x + kv.y * kv.y + kv.z * kv.z + kv.w * kv.w;
        }
    }
#pragma unroll
    for (int off = 16; off > 0; off >>= 1)
        kn = fmaxf(kn, __shfl_xor_sync(0xffffffffu, kn, off));
    if ((tid & 31) == 0) red[tid >> 5] = kn;
    __syncthreads();
    float kmax2 = fmaxf(fmaxf(fmaxf(red[0], red[1]), fmaxf(red[2], red[3])),
                        fmaxf(fmaxf(red[4], red[5]), fmaxf(red[6], red[7])));

    float qn2 = 0.f;
#pragma unroll
    for (int c = 0; c < HSn; c++) qn2 = fmaf(q[c], q[c], qn2);
    float m0 = sqrtf(qn2 * kmax2);   // Cauchy-Schwarz bound: >= all scores

    float l = 0.0f;
    float o[HSP];
#pragma unroll
    for (int c = 0; c < HSP; c++) o[c] = 0.0f;

    for (int j = 0; j <= tid; j++) {
        const float4* kr = (const float4*)(Ks + j * HSP);
        float s0 = 0.f, s1 = 0.f, s2 = 0.f, s3 = 0.f;
#pragma unroll
        for (int u = 0; u < 11; u++) {
            float4 kv = kr[u];
            s0 = fmaf(q[4*u],   kv.x, s0);
            s1 = fmaf(q[4*u+1], kv.y, s1);
            s2 = fmaf(q[4*u+2], kv.z, s2);
            s3 = fmaf(q[4*u+3], kv.w, s3);
        }
        float s = (s0 + s1) + (s2 + s3);
        float p = __expf(fmaxf(s - m0, -80.0f));
        l += p;
        const float4* vr = (const float4*)(Vs + j * HSP);
#pragma unroll
        for (int u = 0; u < 11; u++) {
            float4 vv = vr[u];
            o[4*u]   = fmaf(p, vv.x, o[4*u]);
            o[4*u+1] = fmaf(p, vv.y, o[4*u+1]);
            o[4*u+2] = fmaf(p, vv.z, o[4*u+2]);
            o[4*u+3] = fmaf(p, vv.w, o[4*u+3]);
        }
    }

    float inv = 1.0f / l;
    float* op = heads + ((size_t)(b * Sn + tid)) * Dn + h * HSn;
#pragma unroll
    for (int c = 0; c < HSn; c++) op[c] = o[c] * inv;
    if (h == 0) {
        float* zp = heads + ((size_t)(b * Sn + tid)) * Dn;
        zp[252] = 0.f; zp[253] = 0.f; zp[254] = 0.f; zp[255] = 0.f;
    }
}

// ---------------------------------------------------------------------------
// LayerNorm over last dim (256): one warp per row.
// ---------------------------------------------------------------------------
__global__ void ln_kernel(const float* __restrict__ in, const float* __restrict__ g,
                          const float* __restrict__ bb, float* __restrict__ out) {
    int row = blockIdx.x * blockDim.y + threadIdx.y;
    int lane = threadIdx.x;
    const float4* x = (const float4*)(in + (size_t)row * Dn);
    float4 a = x[lane];
    float4 c = x[lane + 32];
    float s  = a.x + a.y + a.z + a.w + c.x + c.y + c.z + c.w;
    float ss = a.x*a.x + a.y*a.y + a.z*a.z + a.w*a.w
             + c.x*c.x + c.y*c.y + c.z*c.z + c.w*c.w;
#pragma unroll
    for (int off = 16; off > 0; off >>= 1) {
        s  += __shfl_xor_sync(0xffffffffu, s,  off);
        ss += __shfl_xor_sync(0xffffffffu, ss, off);
    }
    float mean = s * (1.0f / 256.0f);
    float var  = ss * (1.0f / 256.0f) - mean * mean;
    float rstd = rsqrtf(var + 1e-5f);
    float4 g1 = ((const float4*)g)[lane],  g2 = ((const float4*)g)[lane + 32];
    float4 b1 = ((const float4*)bb)[lane], b2 = ((const float4*)bb)[lane + 32];
    float4 r1, r2;
    r1.x = (a.x - mean) * rstd * g1.x + b1.x;
    r1.y = (a.y - mean) * rstd * g1.y + b1.y;
    r1.z = (a.z - mean) * rstd * g1.z + b1.z;
    r1.w = (a.w - mean) * rstd * g1.w + b1.w;
    r2.x = (c.x - mean) * rstd * g2.x + b2.x;
    r2.y = (c.y - mean) * rstd * g2.y + b2.y;
    r2.z = (c.z - mean) * rstd * g2.z + b2.z;
    r2.w = (c.w - mean) * rstd * g2.w + b2.w;
    float4* o4 = (float4*)(out + (size_t)row * Dn);
    o4[lane] = r1;
    o4[lane + 32] = r2;
}

// ---------------------------------------------------------------------------
// Launch
// ---------------------------------------------------------------------------
extern "C" void kernel_launch(void* const* d_in, const int* in_sizes, int n_in,
                              void* d_out, int out_size) {
    const float* x     = (const float*)d_in[0];
    const float* Wq    = (const float*)d_in[1];
    const float* Wk    = (const float*)d_in[2];
    const float* Wv    = (const float*)d_in[3];
    const float* Wproj = (const float*)d_in[4];
    const float* bproj = (const float*)d_in[5];
    const float* ln1_g = (const float*)d_in[6];
    const float* ln1_b = (const float*)d_in[7];
    const float* W1    = (const float*)d_in[8];
    const float* b1    = (const float*)d_in[9];
    const float* W2    = (const float*)d_in[10];
    const float* b2    = (const float*)d_in[11];
    const float* ln2_g = (const float*)d_in[12];
    const float* ln2_b = (const float*)d_in[13];
    float* out = (float*)d_out;

    float *qkv, *heads, *res1, *ln1, *ff1, *res2, *wqkv, *wproj;
    cudaGetSymbolAddress((void**)&qkv,   g_qkv);
    cudaGetSymbolAddress((void**)&heads, g_heads);
    cudaGetSymbolAddress((void**)&res1,  g_res1);
    cudaGetSymbolAddress((void**)&ln1,   g_ln1);
    cudaGetSymbolAddress((void**)&ff1,   g_ff1);
    cudaGetSymbolAddress((void**)&res2,  g_res2);
    cudaGetSymbolAddress((void**)&wqkv,  g_wqkv);
    cudaGetSymbolAddress((void**)&wproj, g_wproj);

    int smem_attn = 2 * Sn * HSP * (int)sizeof(float);   // 90112 B
    cudaFuncSetAttribute(attn_kernel, cudaFuncAttributeMaxDynamicSharedMemorySize, smem_attn);

    // 1. pack weights
    pack_kernel<<<768, 256>>>(Wq, Wk, Wv, Wproj, wqkv, wproj);
    // 2. QKV:   [32768,256] @ [256,768]
    gemm_tc<0><<<dim3(NQKVP / 64, Mrows / 128), 256>>>(x, wqkv, qkv, nullptr, nullptr, Mrows, NQKVP, Dn);
    // 3. attention -> head_cat
    attn_kernel<<<dim3(Bn, Hn), 256, smem_attn>>>(qkv, heads);
    // 4. proj + residual(x)
    gemm_tc<2><<<dim3(Dn / 64, Mrows / 128), 256>>>(heads, wproj, res1, bproj, x, Mrows, Dn, Dn);
    // 5. LN1
    ln_kernel<<<Mrows / 8, dim3(32, 8)>>>(res1, ln1_g, ln1_b, ln1);
    // 6. FFN1 + ReLU
    gemm_tc<1><<<dim3(DFFn / 64, Mrows / 128), 256>>>(ln1, W1, ff1, b1, nullptr, Mrows, DFFn, Dn);
    // 7. FFN2 + residual(ln1)
    gemm_tc<2><<<dim3(Dn / 64, Mrows / 128), 256>>>(ff1, W2, res2, b2, ln1, Mrows, Dn, DFFn);
    // 8. LN2 -> output
    ln_kernel<<<Mrows / 8, dim3(32, 8)>>>(res2, ln2_g, ln2_b, out);
}

// round 4
// speedup vs baseline: 1.8336x; 1.0174x over previous
#include <cuda_runtime.h>
#include <cuda_fp16.h>
#include <math.h>
#include <stdint.h>

// Problem constants
#define Bn    128
#define Sn    256
#define Dn    256
#define Hn    6
#define HSn   42
#define HC    252        // Hn*HSn
#define NQKVP 768        // 3*HC = 756, padded to 768 for tile-exact GEMM
#define DFFn  1024
#define Mrows 32768      // Bn*Sn
#define BHn   (Bn*Hn)    // 768

// ---------------------------------------------------------------------------
// Scratch (allocation-free: __device__ globals)
// ---------------------------------------------------------------------------
__device__ float  g_qkv  [(size_t)Mrows * NQKVP];  // [M, 768] q|k|v head-concat
__device__ float  g_heads[(size_t)Mrows * Dn];     // [M, 256] head_cat (cols 252..255 = 0)
__device__ float  g_res1 [(size_t)Mrows * Dn];
__device__ float  g_ln1  [(size_t)Mrows * Dn];
__device__ float  g_ff1  [(size_t)Mrows * DFFn];
__device__ float  g_res2 [(size_t)Mrows * Dn];
__device__ float  g_wqkv [Dn * NQKVP];
__device__ float  g_wproj[Dn * Dn];
__device__ float  g_m0   [BHn * Sn];               // per-row softmax bound
__device__ float  g_l    [BHn * Sn];               // per-row sum of exp
__device__ __half g_P    [(size_t)BHn * Sn * Sn];  // attention probs (unnormalized)

// ---------------------------------------------------------------------------
// tf32 helpers
// ---------------------------------------------------------------------------
__device__ __forceinline__ uint32_t f2tf(float f) {
    uint32_t u;
    asm("cvt.rna.tf32.f32 %0, %1;" : "=r"(u) : "f"(f));
    return u;
}
__device__ __forceinline__ void mma_tf32(float c[4], const uint32_t a[4], const uint32_t b[2]) {
    asm volatile(
        "mma.sync.aligned.m16n8k8.row.col.f32.tf32.tf32.f32 "
        "{%0,%1,%2,%3}, {%4,%5,%6,%7}, {%8,%9}, {%0,%1,%2,%3};"
        : "+f"(c[0]), "+f"(c[1]), "+f"(c[2]), "+f"(c[3])
        : "r"(a[0]), "r"(a[1]), "r"(a[2]), "r"(a[3]), "r"(b[0]), "r"(b[1]));
}

// ---------------------------------------------------------------------------
// Weight packing + zero g_heads pad columns
// ---------------------------------------------------------------------------
__global__ void pack_kernel(const float* __restrict__ Wq, const float* __restrict__ Wk,
                            const float* __restrict__ Wv, const float* __restrict__ Wproj,
                            float* __restrict__ wqkv, float* __restrict__ wproj_p,
                            float* __restrict__ heads) {
    int idx = blockIdx.x * 256 + threadIdx.x;
    if (idx < Dn * NQKVP) {
        int d = idx / NQKVP, j = idx % NQKVP;
        float val = 0.0f;
        if (j < 756) {
            int which = j / HC;
            int rr = j - which * HC;
            int h = rr / HSn, c = rr - h * HSn;
            const float* W = (which == 0) ? Wq : (which == 1) ? Wk : Wv;
            val = W[(h * Dn + d) * HSn + c];
        }
        wqkv[idx] = val;
    }
    if (idx < Dn * Dn) {
        int rr = idx / Dn, c = idx % Dn;
        wproj_p[idx] = (rr < HC) ? Wproj[rr * Dn + c] : 0.0f;
    }
    if (idx < Mrows)   // zero head_cat pad cols 252..255
        *(float4*)&heads[(size_t)idx * Dn + 252] = make_float4(0.f, 0.f, 0.f, 0.f);
}

// ---------------------------------------------------------------------------
// tf32 tensor-core GEMM: C[M,N] = A[M,K] @ B[K,N] (+ epilogue)  (unchanged)
// ---------------------------------------------------------------------------
#define LDA 20
#define LDB 72

template<int MODE>
__global__ __launch_bounds__(256) void gemm_tc(
    const float* __restrict__ A, const float* __restrict__ B, float* __restrict__ C,
    const float* __restrict__ bias, const float* __restrict__ resid,
    int M, int N, int K)
{
    __shared__ uint32_t As[2][128 * LDA];
    __shared__ uint32_t Bs[2][16 * LDB];

    int tid  = threadIdx.x;
    int lane = tid & 31, wid = tid >> 5;
    int wm = wid & 3, wn = wid >> 2;
    int bm = blockIdx.y * 128, bn = blockIdx.x * 64;
    int r  = lane >> 2, cq = lane & 3;

    float acc[2][4][4];
#pragma unroll
    for (int mf = 0; mf < 2; mf++)
#pragma unroll
        for (int nf = 0; nf < 4; nf++)
#pragma unroll
            for (int i = 0; i < 4; i++) acc[mf][nf][i] = 0.0f;

    int a_r = tid >> 2;
    int a_c = (tid & 3) << 2;
    int b_r = tid >> 4;
    int b_c = (tid & 15) << 2;

    const float* Ag0 = A + (size_t)(bm + a_r) * K + a_c;
    const float* Ag1 = A + (size_t)(bm + a_r + 64) * K + a_c;
    const float* Bg  = B + (size_t)b_r * N + bn + b_c;

    float4 ra0, ra1, rb;
    ra0 = *(const float4*)(Ag0);
    ra1 = *(const float4*)(Ag1);
    rb  = *(const float4*)(Bg);
    {
        uint4 u0 = make_uint4(f2tf(ra0.x), f2tf(ra0.y), f2tf(ra0.z), f2tf(ra0.w));
        uint4 u1 = make_uint4(f2tf(ra1.x), f2tf(ra1.y), f2tf(ra1.z), f2tf(ra1.w));
        uint4 ub = make_uint4(f2tf(rb.x),  f2tf(rb.y),  f2tf(rb.z),  f2tf(rb.w));
        *(uint4*)&As[0][a_r * LDA + a_c]        = u0;
        *(uint4*)&As[0][(a_r + 64) * LDA + a_c] = u1;
        *(uint4*)&Bs[0][b_r * LDB + b_c]        = ub;
    }
    __syncthreads();

    int nk = K >> 4;
    for (int it = 0; it < nk; it++) {
        int cur = it & 1, nxt = cur ^ 1;
        bool more = (it + 1 < nk);
        if (more) {
            int k0 = (it + 1) << 4;
            ra0 = *(const float4*)(Ag0 + k0);
            ra1 = *(const float4*)(Ag1 + k0);
            rb  = *(const float4*)(Bg + (size_t)k0 * N);
        }
#pragma unroll
        for (int kk = 0; kk < 16; kk += 8) {
            uint32_t a[2][4], b[4][2];
#pragma unroll
            for (int mf = 0; mf < 2; mf++) {
                int ar = (wm * 32 + mf * 16 + r) * LDA + kk + cq;
                a[mf][0] = As[cur][ar];
                a[mf][1] = As[cur][ar + 8 * LDA];
                a[mf][2] = As[cur][ar + 4];
                a[mf][3] = As[cur][ar + 8 * LDA + 4];
            }
#pragma unroll
            for (int nf = 0; nf < 4; nf++) {
                int bc = (kk + cq) * LDB + wn * 32 + nf * 8 + r;
                b[nf][0] = Bs[cur][bc];
                b[nf][1] = Bs[cur][bc + 4 * LDB];
            }
#pragma unroll
            for (int mf = 0; mf < 2; mf++)
#pragma unroll
                for (int nf = 0; nf < 4; nf++)
                    mma_tf32(acc[mf][nf], a[mf], b[nf]);
        }
        if (more) {
            uint4 u0 = make_uint4(f2tf(ra0.x), f2tf(ra0.y), f2tf(ra0.z), f2tf(ra0.w));
            uint4 u1 = make_uint4(f2tf(ra1.x), f2tf(ra1.y), f2tf(ra1.z), f2tf(ra1.w));
            uint4 ub = make_uint4(f2tf(rb.x),  f2tf(rb.y),  f2tf(rb.z),  f2tf(rb.w));
            *(uint4*)&As[nxt][a_r * LDA + a_c]        = u0;
            *(uint4*)&As[nxt][(a_r + 64) * LDA + a_c] = u1;
            *(uint4*)&Bs[nxt][b_r * LDB + b_c]        = ub;
        }
        __syncthreads();
    }

#pragma unroll
    for (int mf = 0; mf < 2; mf++) {
#pragma unroll
        for (int nf = 0; nf < 4; nf++) {
            int row = bm + wm * 32 + mf * 16 + r;
            int col = bn + wn * 32 + nf * 8 + cq * 2;
            float v0 = acc[mf][nf][0], v1 = acc[mf][nf][1];
            float v2 = acc[mf][nf][2], v3 = acc[mf][nf][3];
            size_t o0 = (size_t)row * N + col;
            size_t o1 = (size_t)(row + 8) * N + col;
            if (MODE == 1) {
                float b0 = bias[col], b1 = bias[col + 1];
                v0 = fmaxf(v0 + b0, 0.f); v1 = fmaxf(v1 + b1, 0.f);
                v2 = fmaxf(v2 + b0, 0.f); v3 = fmaxf(v3 + b1, 0.f);
            }
            if (MODE == 2) {
                float b0 = bias[col], b1 = bias[col + 1];
                float2 r0 = *(const float2*)(resid + o0);
                float2 r1 = *(const float2*)(resid + o1);
                v0 += b0 + r0.x; v1 += b1 + r0.y;
                v2 += b0 + r1.x; v3 += b1 + r1.y;
            }
            *(float2*)(C + o0) = make_float2(v0, v1);
            *(float2*)(C + o1) = make_float2(v2, v3);
        }
    }
}

// ---------------------------------------------------------------------------
// Attention prep: m0[b,h,i] = |q_i*scale| * max_j |k_j|  (Cauchy-Schwarz
// upper bound on all scores of row i); also zero the row-sum accumulator.
// ---------------------------------------------------------------------------
__global__ void attn_prep(const float* __restrict__ qkv,
                          float* __restrict__ m0v, float* __restrict__ lv) {
    __shared__ float red[8];
    int b = blockIdx.x, h = blockIdx.y;
    int t = threadIdx.x;
    const float scale = rsqrtf(42.0f);
    const float* base = qkv + (size_t)b * Sn * NQKVP;

    const float* kp = base + (size_t)t * NQKVP + HC + h * HSn;
    float kn = 0.f;
#pragma unroll
    for (int c = 0; c < HSn; c++) kn = fmaf(kp[c], kp[c], kn);
#pragma unroll
    for (int off = 16; off > 0; off >>= 1)
        kn = fmaxf(kn, __shfl_xor_sync(0xffffffffu, kn, off));
    if ((t & 31) == 0) red[t >> 5] = kn;
    __syncthreads();
    float kmax2 = fmaxf(fmaxf(fmaxf(red[0], red[1]), fmaxf(red[2], red[3])),
                        fmaxf(fmaxf(red[4], red[5]), fmaxf(red[6], red[7])));

    const float* qp = base + (size_t)t * NQKVP + h * HSn;
    float qn = 0.f;
#pragma unroll
    for (int c = 0; c < HSn; c++) {
        float v = qp[c] * scale;
        qn = fmaf(v, v, qn);
    }
    int bh = b * Hn + h;
    m0v[bh * Sn + t] = sqrtf(qn * kmax2);
    lv[bh * Sn + t]  = 0.f;
}

// ---------------------------------------------------------------------------
// Attention scores: P = exp(Q_scaled @ K^T - m0) (causal), fp16 out, + row
// sums via atomics. One block per (b,h, tile); tile in {(0,0),(0,1),(1,0..3)}.
// BM=128, BN=64, K=48 (single shot). 8 warps (4m x 2n), warp tile 32x32.
// ---------------------------------------------------------------------------
#define LDS52 52
__global__ __launch_bounds__(256) void attn_scores(const float* __restrict__ qkv,
                                                   const float* __restrict__ m0v,
                                                   float* __restrict__ lv,
                                                   __half* __restrict__ P) {
    __shared__ uint32_t Qs[128 * LDS52];
    __shared__ uint32_t Ks[64 * LDS52];

    int bh = blockIdx.x;
    int b = bh / Hn, h = bh - b * Hn;
    int tile = blockIdx.y;
    int mi = (tile < 2) ? 0 : 1;
    int ni = (tile < 2) ? tile : tile - 2;
    int bm = mi * 128, bn = ni * 64;

    int tid = threadIdx.x;
    const float scale = rsqrtf(42.0f);
    const float* base = qkv + (size_t)b * Sn * NQKVP;

    for (int idx = tid; idx < 128 * 48; idx += 256) {
        int rr = idx / 48, c = idx - rr * 48;
        float v = (c < HSn) ? base[(size_t)(bm + rr) * NQKVP + h * HSn + c] * scale : 0.f;
        Qs[rr * LDS52 + c] = f2tf(v);
    }
    for (int idx = tid; idx < 64 * 48; idx += 256) {
        int rr = idx / 48, c = idx - rr * 48;
        float v = (c < HSn) ? base[(size_t)(bn + rr) * NQKVP + HC + h * HSn + c] : 0.f;
        Ks[rr * LDS52 + c] = f2tf(v);
    }
    __syncthreads();

    int lane = tid & 31, wid = tid >> 5;
    int wm = wid & 3, wn = wid >> 2;
    int r = lane >> 2, cq = lane & 3;

    float acc[2][4][4];
#pragma unroll
    for (int mf = 0; mf < 2; mf++)
#pragma unroll
        for (int nf = 0; nf < 4; nf++)
#pragma unroll
            for (int i = 0; i < 4; i++) acc[mf][nf][i] = 0.0f;

#pragma unroll
    for (int kk = 0; kk < 48; kk += 8) {
        uint32_t a[2][4], bf[4][2];
#pragma unroll
        for (int mf = 0; mf < 2; mf++) {
            int ar = (wm * 32 + mf * 16 + r) * LDS52 + kk + cq;
            a[mf][0] = Qs[ar];
            a[mf][1] = Qs[ar + 8 * LDS52];
            a[mf][2] = Qs[ar + 4];
            a[mf][3] = Qs[ar + 8 * LDS52 + 4];
        }
#pragma unroll
        for (int nf = 0; nf < 4; nf++) {
            int bc = (wn * 32 + nf * 8 + r) * LDS52 + kk + cq;   // K^T: n-major rows
            bf[nf][0] = Ks[bc];
            bf[nf][1] = Ks[bc + 4];
        }
#pragma unroll
        for (int mf = 0; mf < 2; mf++)
#pragma unroll
            for (int nf = 0; nf < 4; nf++)
                mma_tf32(acc[mf][nf], a[mf], bf[nf]);
    }

    size_t Pbase = (size_t)bh * Sn * Sn;
#pragma unroll
    for (int mf = 0; mf < 2; mf++) {
        int row0 = bm + wm * 32 + mf * 16 + r;
        int row1 = row0 + 8;
        float m00 = m0v[bh * Sn + row0];
        float m01 = m0v[bh * Sn + row1];
        float rs0 = 0.f, rs1 = 0.f;
#pragma unroll
        for (int nf = 0; nf < 4; nf++) {
            int col = bn + wn * 32 + nf * 8 + cq * 2;
            float p00 = (col     <= row0) ? __expf(acc[mf][nf][0] - m00) : 0.f;
            float p01 = (col + 1 <= row0) ? __expf(acc[mf][nf][1] - m00) : 0.f;
            float p10 = (col     <= row1) ? __expf(acc[mf][nf][2] - m01) : 0.f;
            float p11 = (col + 1 <= row1) ? __expf(acc[mf][nf][3] - m01) : 0.f;
            __half h00 = __float2half_rn(p00), h01 = __float2half_rn(p01);
            __half h10 = __float2half_rn(p10), h11 = __float2half_rn(p11);
            rs0 += __half2float(h00) + __half2float(h01);
            rs1 += __half2float(h10) + __half2float(h11);
            *(__half2*)&P[Pbase + (size_t)row0 * Sn + col] = __halves2half2(h00, h01);
            *(__half2*)&P[Pbase + (size_t)row1 * Sn + col] = __halves2half2(h10, h11);
        }
        rs0 += __shfl_xor_sync(0xffffffffu, rs0, 1);
        rs0 += __shfl_xor_sync(0xffffffffu, rs0, 2);
        rs1 += __shfl_xor_sync(0xffffffffu, rs1, 1);
        rs1 += __shfl_xor_sync(0xffffffffu, rs1, 2);
        if (cq == 0) {
            atomicAdd(&lv[bh * Sn + row0], rs0);
            atomicAdd(&lv[bh * Sn + row1], rs1);
        }
    }
}

// ---------------------------------------------------------------------------
// Attention AV: O = (P @ V) / l, scattered into g_heads at col h*42.
// One block per (b,h,mi). BM=128, N=48, K = 128 (mi=0) or 256 (mi=1).
// 8 warps, each 16 rows x 48 cols.
// ---------------------------------------------------------------------------
#define LDP 20
#define LDV 56
__global__ __launch_bounds__(256) void attn_av(const __half* __restrict__ P,
                                               const float* __restrict__ qkv,
                                               const float* __restrict__ lv,
                                               float* __restrict__ heads) {
    __shared__ uint32_t Ps[128 * LDP];
    __shared__ uint32_t Vs[16 * LDV];

    int bh = blockIdx.x;
    int b = bh / Hn, h = bh - b * Hn;
    int mi = blockIdx.y;
    int bm = mi * 128;

    int tid = threadIdx.x, lane = tid & 31, wid = tid >> 5;
    int r = lane >> 2, cq = lane & 3;

    float acc[6][4];
#pragma unroll
    for (int nf = 0; nf < 6; nf++)
#pragma unroll
        for (int i = 0; i < 4; i++) acc[nf][i] = 0.f;

    int nk = (mi == 0) ? 8 : 16;          // causal: rows<128 need keys<128 only
    const __half* Pb = P + (size_t)bh * Sn * Sn;
    const float* vbase = qkv + (size_t)b * Sn * NQKVP + 2 * HC + h * HSn;

    int pr = tid >> 1;                    // P-tile load coords (8 halves/thread)
    int pc = (tid & 1) * 8;

    for (int it = 0; it < nk; it++) {
        int k0 = it * 16;
        {
            uint4 u = *(const uint4*)(Pb + (size_t)(bm + pr) * Sn + k0 + pc);
            __half2 x0 = *(__half2*)&u.x, x1 = *(__half2*)&u.y;
            __half2 x2 = *(__half2*)&u.z, x3 = *(__half2*)&u.w;
            float2 f0 = __half22float2(x0), f1 = __half22float2(x1);
            float2 f2 = __half22float2(x2), f3 = __half22float2(x3);
            uint32_t* dst = &Ps[pr * LDP + pc];
            dst[0] = f2tf(f0.x); dst[1] = f2tf(f0.y);
            dst[2] = f2tf(f1.x); dst[3] = f2tf(f1.y);
            dst[4] = f2tf(f2.x); dst[5] = f2tf(f2.y);
            dst[6] = f2tf(f3.x); dst[7] = f2tf(f3.y);
        }
        for (int idx = tid; idx < 16 * 48; idx += 256) {
            int vr = idx / 48, vc = idx - vr * 48;
            float v = (vc < HSn) ? vbase[(size_t)(k0 + vr) * NQKVP + vc] : 0.f;
            Vs[vr * LDV + vc] = f2tf(v);
        }
        __syncthreads();

#pragma unroll
        for (int kk = 0; kk < 16; kk += 8) {
            uint32_t a[4];
            int ar = (wid * 16 + r) * LDP + kk + cq;
            a[0] = Ps[ar];
            a[1] = Ps[ar + 8 * LDP];
            a[2] = Ps[ar + 4];
            a[3] = Ps[ar + 8 * LDP + 4];
            uint32_t bf[6][2];
#pragma unroll
            for (int nf = 0; nf < 6; nf++) {
                int bc = (kk + cq) * LDV + nf * 8 + r;
                bf[nf][0] = Vs[bc];
                bf[nf][1] = Vs[bc + 4 * LDV];
            }
#pragma unroll
            for (int nf = 0; nf < 6; nf++)
                mma_tf32(acc[nf], a, bf[nf]);
        }
        __syncthreads();
    }

    int row0 = bm + wid * 16 + r;
    int row1 = row0 + 8;
    float li0 = 1.0f / lv[bh * Sn + row0];
    float li1 = 1.0f / lv[bh * Sn + row1];
#pragma unroll
    for (int nf = 0; nf < 6; nf++) {
        int col = nf * 8 + cq * 2;
        if (col < HSn) {
            *(float2*)&heads[(size_t)(b * Sn + row0) * Dn + h * HSn + col] =
                make_float2(acc[nf][0] * li0, acc[nf][1] * li0);
            *(float2*)&heads[(size_t)(b * Sn + row1) * Dn + h * HSn + col] =
                make_float2(acc[nf][2] * li1, acc[nf][3] * li1);
        }
    }
}

// ---------------------------------------------------------------------------
// LayerNorm over last dim (256): one warp per row.
// ---------------------------------------------------------------------------
__global__ void ln_kernel(const float* __restrict__ in, const float* __restrict__ g,
                          const float* __restrict__ bb, float* __restrict__ out) {
    int row = blockIdx.x * blockDim.y + threadIdx.y;
    int lane = threadIdx.x;
    const float4* x = (const float4*)(in + (size_t)row * Dn);
    float4 a = x[lane];
    float4 c = x[lane + 32];
    float s  = a.x + a.y + a.z + a.w + c.x + c.y + c.z + c.w;
    float ss = a.x*a.x + a.y*a.y + a.z*a.z + a.w*a.w
             + c.x*c.x + c.y*c.y + c.z*c.z + c.w*c.w;
#pragma unroll
    for (int off = 16; off > 0; off >>= 1) {
        s  += __shfl_xor_sync(0xffffffffu, s,  off);
        ss += __shfl_xor_sync(0xffffffffu, ss, off);
    }
    float mean = s * (1.0f / 256.0f);
    float var  = ss * (1.0f / 256.0f) - mean * mean;
    float rstd = rsqrtf(var + 1e-5f);
    float4 g1 = ((const float4*)g)[lane],  g2 = ((const float4*)g)[lane + 32];
    float4 b1 = ((const float4*)bb)[lane], b2 = ((const float4*)bb)[lane + 32];
    float4 r1, r2;
    r1.x = (a.x - mean) * rstd * g1.x + b1.x;
    r1.y = (a.y - mean) * rstd * g1.y + b1.y;
    r1.z = (a.z - mean) * rstd * g1.z + b1.z;
    r1.w = (a.w - mean) * rstd * g1.w + b1.w;
    r2.x = (c.x - mean) * rstd * g2.x + b2.x;
    r2.y = (c.y - mean) * rstd * g2.y + b2.y;
    r2.z = (c.z - mean) * rstd * g2.z + b2.z;
    r2.w = (c.w - mean) * rstd * g2.w + b2.w;
    float4* o4 = (float4*)(out + (size_t)row * Dn);
    o4[lane] = r1;
    o4[lane + 32] = r2;
}

// ---------------------------------------------------------------------------
// Launch
// ---------------------------------------------------------------------------
extern "C" void kernel_launch(void* const* d_in, const int* in_sizes, int n_in,
                              void* d_out, int out_size) {
    const float* x     = (const float*)d_in[0];
    const float* Wq    = (const float*)d_in[1];
    const float* Wk    = (const float*)d_in[2];
    const float* Wv    = (const float*)d_in[3];
    const float* Wproj = (const float*)d_in[4];
    const float* bproj = (const float*)d_in[5];
    const float* ln1_g = (const float*)d_in[6];
    const float* ln1_b = (const float*)d_in[7];
    const float* W1    = (const float*)d_in[8];
    const float* b1    = (const float*)d_in[9];
    const float* W2    = (const float*)d_in[10];
    const float* b2    = (const float*)d_in[11];
    const float* ln2_g = (const float*)d_in[12];
    const float* ln2_b = (const float*)d_in[13];
    float* out = (float*)d_out;

    float *qkv, *heads, *res1, *ln1, *ff1, *res2, *wqkv, *wproj, *m0v, *lv;
    __half* Pp;
    cudaGetSymbolAddress((void**)&qkv,   g_qkv);
    cudaGetSymbolAddress((void**)&heads, g_heads);
    cudaGetSymbolAddress((void**)&res1,  g_res1);
    cudaGetSymbolAddress((void**)&ln1,   g_ln1);
    cudaGetSymbolAddress((void**)&ff1,   g_ff1);
    cudaGetSymbolAddress((void**)&res2,  g_res2);
    cudaGetSymbolAddress((void**)&wqkv,  g_wqkv);
    cudaGetSymbolAddress((void**)&wproj, g_wproj);
    cudaGetSymbolAddress((void**)&m0v,   g_m0);
    cudaGetSymbolAddress((void**)&lv,    g_l);
    cudaGetSymbolAddress((void**)&Pp,    g_P);

    // 1. pack weights (+ zero head_cat pad cols)
    pack_kernel<<<768, 256>>>(Wq, Wk, Wv, Wproj, wqkv, wproj, heads);
    // 2. QKV:   [32768,256] @ [256,768]
    gemm_tc<0><<<dim3(NQKVP / 64, Mrows / 128), 256>>>(x, wqkv, qkv, nullptr, nullptr, Mrows, NQKVP, Dn);
    // 3a. attention prep (m0 bound + zero l)
    attn_prep<<<dim3(Bn, Hn), 256>>>(qkv, m0v, lv);
    // 3b. scores + exp -> P (fp16), row sums -> l
    attn_scores<<<dim3(BHn, 6), 256>>>(qkv, m0v, lv, Pp);
    // 3c. AV -> head_cat
    attn_av<<<dim3(BHn, 2), 256>>>(Pp, qkv, lv, heads);
    // 4. proj + residual(x)
    gemm_tc<2><<<dim3(Dn / 64, Mrows / 128), 256>>>(heads, wproj, res1, bproj, x, Mrows, Dn, Dn);
    // 5. LN1
    ln_kernel<<<Mrows / 8, dim3(32, 8)>>>(res1, ln1_g, ln1_b, ln1);
    // 6. FFN1 + ReLU
    gemm_tc<1><<<dim3(DFFn / 64, Mrows / 128), 256>>>(ln1, W1, ff1, b1, nullptr, Mrows, DFFn, Dn);
    // 7. FFN2 + residual(ln1)
    gemm_tc<2><<<dim3(Dn / 64, Mrows / 128), 256>>>(ff1, W2, res2, b2, ln1, Mrows, Dn, DFFn);
    // 8. LN2 -> output
    ln_kernel<<<Mrows / 8, dim3(32, 8)>>>(res2, ln2_g, ln2_b, out);
}